// round 12
// baseline (speedup 1.0000x reference)
#include <cuda_runtime.h>
#include <math.h>

#define BB    16
#define NBB   512
#define KK    32
#define NBLK  (BB * NBB)      /* 8192 (b, nb) blocks */
#define GW    0.3f
#define G1    1024            /* K1 grid: 1 warp per block */
#define G2    128             /* K2 grid: 8 q-blocks per warp */
#define TPB   256

/* ---- scratch (device globals; no allocation) ---- */
__device__ float2 g_vp   [NBLK];    /* (cnt_vld, sum_vld_p) */
__device__ float4 g_uncs [NBLK];    /* (sum_unc_p, sum_unc_p2, cnt_unc, 0) */
__device__ float2 g_bce1 [G1];      /* K1 per-CTA (bce_sum, bce_cnt) */
__device__ float2 g_sq2  [G2];      /* K2 per-CTA (sq, qu) — single batch each */
__device__ unsigned int g_done = 0;

/* reduce two floats simultaneously: 2 shfl + 1 packed f32x2 add per level */
__device__ __forceinline__ void warp_sum2(float& a, float& b) {
    unsigned long long p;
    asm("mov.b64 %0, {%1, %2};" : "=l"(p) : "f"(a), "f"(b));
    #pragma unroll
    for (int o = 16; o > 0; o >>= 1) {
        unsigned int lo = (unsigned int)p, hi = (unsigned int)(p >> 32);
        lo = __shfl_down_sync(0xFFFFFFFFu, lo, o);
        hi = __shfl_down_sync(0xFFFFFFFFu, hi, o);
        unsigned long long q = ((unsigned long long)hi << 32) | lo;
        asm("add.rn.f32x2 %0, %1, %2;" : "=l"(p) : "l"(p), "l"(q));
    }
    asm("mov.b64 {%0, %1}, %2;" : "=f"(a), "=f"(b) : "l"(p));
}

__device__ __forceinline__ unsigned int arrive_acq_rel(unsigned int* ctr) {
    unsigned int old;
    asm volatile("atom.acq_rel.gpu.add.u32 %0, [%1], 1;"
                 : "=r"(old) : "l"(ctr) : "memory");
    return old;
}

/* ================= K1: per-block stats, 1 warp per 128-elem block ========== */
__global__ void __launch_bounds__(TPB) k1_stats(
    const float4* __restrict__ logits,
    const float4* __restrict__ targets,
    const int4*   __restrict__ sup_mask,
    const int4*   __restrict__ ign_mask)
{
    const int lane = threadIdx.x & 31;
    const int wid  = threadIdx.x >> 5;
    const int blk  = blockIdx.x * 8 + wid;
    const int v    = blk * 32 + lane;

    const float4 x4 = logits[v];
    const float4 t4 = targets[v];
    const int4   s4 = sup_mask[v];
    const int4   i4 = ign_mask[v];

    float svp = 0.f, sup_ = 0.f, sup2 = 0.f, bce = 0.f, cnts = 0.f;
    const float xs[4] = {x4.x, x4.y, x4.z, x4.w};
    const float ts[4] = {t4.x, t4.y, t4.z, t4.w};
    const int   ss[4] = {s4.x, s4.y, s4.z, s4.w};
    const int   is_[4]= {i4.x, i4.y, i4.z, i4.w};

    #pragma unroll
    for (int j = 0; j < 4; ++j) {
        const float x  = xs[j];
        const bool  su = ss[j] != 0;
        const bool  ig = is_[j] != 0;
        const bool  vld = !ig;
        const bool  unc = vld && !su;
        const float p = __fdividef(1.0f, 1.0f + __expf(-x));
        if (vld) svp += p;
        if (unc) { sup_ += p; sup2 = fmaf(p, p, sup2); }
        /* targets are exactly 0.0 or 1.0: BCE = -log(t ? p : 1-p) */
        if (su)  bce -= __logf(ts[j] > 0.5f ? p : 1.0f - p);
        /* pack counts: vld + 256*unc + 65536*sup (sum < 2^24, exact) */
        cnts += (vld ? 1.0f : 0.0f) + (unc ? 256.0f : 0.0f) + (su ? 65536.0f : 0.0f);
    }

    float svp2 = svp, d0 = sup_, d1 = sup2, d2 = bce, d3 = cnts;
    warp_sum2(svp2, d3);     /* (sum_vld_p, cnts) */
    warp_sum2(d0, d1);       /* (sum_unc_p, sum_unc_p2) */
    d2 += 0.f;
    float bsum = d2, dummy = 0.f;
    warp_sum2(bsum, dummy);

    __shared__ float2 sh_bce[8];
    if (lane == 0) {
        const int ci = (int)d3;
        g_vp  [blk] = make_float2((float)(ci & 255), svp2);
        g_uncs[blk] = make_float4(d0, d1, (float)((ci >> 8) & 255), 0.f);
        sh_bce[wid] = make_float2(bsum, (float)(ci >> 16));
    }
    __syncthreads();
    if (threadIdx.x == 0) {
        float s = 0.f, c = 0.f;
        #pragma unroll
        for (int w = 0; w < 8; ++w) { s += sh_bce[w].x; c += sh_bce[w].y; }
        g_bce1[blockIdx.x] = make_float2(s, c);
    }
}

/* ============ K2: gather + per-batch sq, then last-CTA final tail ========== */
__global__ void __launch_bounds__(TPB) k2_graph(
    const int* __restrict__ kv_indices,
    const int* __restrict__ kv_num_blocks,
    float*     __restrict__ out)
{
    const int lane = threadIdx.x & 31;
    const int wid  = threadIdx.x >> 5;
    /* warp handles 8 consecutive q-blocks, all in one batch (8 | 512) */
    const int q0 = (blockIdx.x * 8 + wid) * 8;
    const int base = (q0 >> 9) << 9;

    float sq_acc = 0.f, qu_acc = 0.f;

    /* software pipeline: prefetch iter i+1's indices during iter i */
    int idx_n = kv_indices[q0 * KK + lane];
    int knb_n = kv_num_blocks[q0];

    #pragma unroll
    for (int it = 0; it < 8; ++it) {
        const int q   = q0 + it;
        const int idx = idx_n;
        const int knb = knb_n;
        float2 vp = g_vp[base + idx];               /* L2 gather, issued early */
        if (it < 7) {
            idx_n = kv_indices[(q + 1) * KK + lane];
            knb_n = kv_num_blocks[q + 1];
        }
        float4 u;
        if (lane == 0) u = g_uncs[q];

        if (lane >= knb) { vp.x = 0.f; vp.y = 0.f; }
        float cv = vp.x, sp = vp.y;
        warp_sum2(cv, sp);

        if (lane == 0) {
            const float nm = __fdividef(sp, fmaxf(cv, 1.0f));
            const bool ok = (u.z > 0.f) && (knb > 0) && (cv > 0.f);
            const float sq = u.y - 2.0f * nm * u.x + nm * nm * u.z;
            if (ok) { sq_acc += sq; qu_acc += u.z; }
        }
    }

    __shared__ float2 sh_sq[8];
    __shared__ bool   is_last;
    if (lane == 0) sh_sq[wid] = make_float2(sq_acc, qu_acc);
    __syncthreads();
    if (threadIdx.x == 0) {
        float s = 0.f, q = 0.f;
        #pragma unroll
        for (int i = 0; i < 8; ++i) { s += sh_sq[i].x; q += sh_sq[i].y; }
        g_sq2[blockIdx.x] = make_float2(s, q);      /* CTA = 64 q-blocks = 1 batch slice */
        const unsigned int old = arrive_acq_rel(&g_done);
        is_last = (old == G2 - 1);
    }
    __syncthreads();
    if (!is_last) return;

    /* ---------- final tail: deterministic fixed-order ---------- */
    __shared__ float bsq[BB], bqu[BB];
    __shared__ float s_bce;

    /* BCE over K1's 1024 partials: warp 1 */
    if (wid == 1) {
        float bs = 0.f, bc = 0.f;
        #pragma unroll
        for (int i = 0; i < G1 / 32; ++i) {         /* 32 iters, coalesced */
            const float2 p = g_bce1[lane + 32 * i];
            bs += p.x; bc += p.y;
        }
        warp_sum2(bs, bc);
        if (lane == 0) s_bce = __fdividef(bs, fmaxf(bc, 1.0f));
    }

    /* per-batch (sq,qu): 8 CTA-partials per batch; warp 0, lane b<16 */
    if (wid == 0) {
        float sq = 0.f, qu = 0.f;
        if (lane < BB) {
            #pragma unroll
            for (int i = 0; i < 8; ++i) {           /* 128/16 = 8 CTAs per batch */
                const float2 p = g_sq2[lane * 8 + i];
                sq += p.x; qu += p.y;
            }
        }
        bsq[lane & 15] = 0.f;                        /* init then overwrite */
        if (lane < BB) { bsq[lane] = sq; bqu[lane] = qu; }
    }
    __syncthreads();

    if (threadIdx.x == 0) {
        float acc = 0.f, nv = 0.f;
        #pragma unroll
        for (int b2 = 0; b2 < BB; ++b2) {
            if (bqu[b2] > 0.0f) {
                acc += __fdividef(bsq[b2], fmaxf(bqu[b2], 1.0f));
                nv  += 1.0f;
            }
        }
        out[0] = s_bce + GW * __fdividef(acc, fmaxf(nv, 1.0f));
        g_done = 0;   /* self-reset for graph replay */
    }
}

extern "C" void kernel_launch(void* const* d_in, const int* in_sizes, int n_in,
                              void* d_out, int out_size)
{
    const float4* logits        = (const float4*)d_in[0];
    const float4* targets       = (const float4*)d_in[1];
    const int4*   sup_mask      = (const int4*)d_in[2];
    const int4*   ign_mask      = (const int4*)d_in[3];
    const int*    kv_indices    = (const int*)d_in[4];
    const int*    kv_num_blocks = (const int*)d_in[5];
    float* out = (float*)d_out;

    k1_stats<<<G1, TPB>>>(logits, targets, sup_mask, ign_mask);
    k2_graph<<<G2, TPB>>>(kv_indices, kv_num_blocks, out);
}

// round 13
// speedup vs baseline: 1.1572x; 1.1572x over previous
#include <cuda_runtime.h>
#include <math.h>

#define BB    16
#define NBB   512
#define KK    32
#define NBLK  (BB * NBB)      /* 8192 (b, nb) blocks */
#define GW    0.3f
#define GRID  512             /* 32 CTAs per batch; 4 CTAs/SM resident */
#define TPB   256
#define CTAB  32              /* CTAs per batch */

/* ---- scratch (device globals; no allocation) ---- */
__device__ float2 g_vp     [NBLK];  /* (cnt_vld, sum_vld_p) */
__device__ float2 g_cta_bce[GRID];  /* per-CTA (bce_sum, bce_cnt) */
__device__ float2 g_cta_sq [GRID];  /* per-CTA (sq, qu) */
__device__ float4 g_batch  [BB];    /* per-batch (sq, qu, bce_sum, bce_cnt) */
__device__ unsigned int g_barA[BB]; /* phase-A batch barrier */
__device__ unsigned int g_barB[BB]; /* phase-B batch completion */
__device__ unsigned int g_gdone = 0;

/* reduce two floats simultaneously: 2 shfl + 1 packed f32x2 add per level */
__device__ __forceinline__ void warp_sum2(float& a, float& b) {
    unsigned long long p;
    asm("mov.b64 %0, {%1, %2};" : "=l"(p) : "f"(a), "f"(b));
    #pragma unroll
    for (int o = 16; o > 0; o >>= 1) {
        unsigned int lo = (unsigned int)p, hi = (unsigned int)(p >> 32);
        lo = __shfl_down_sync(0xFFFFFFFFu, lo, o);
        hi = __shfl_down_sync(0xFFFFFFFFu, hi, o);
        unsigned long long q = ((unsigned long long)hi << 32) | lo;
        asm("add.rn.f32x2 %0, %1, %2;" : "=l"(p) : "l"(p), "l"(q));
    }
    asm("mov.b64 {%0, %1}, %2;" : "=f"(a), "=f"(b) : "l"(p));
}

__device__ __forceinline__ unsigned int arrive_acq_rel(unsigned int* ctr) {
    unsigned int old;
    asm volatile("atom.acq_rel.gpu.add.u32 %0, [%1], 1;"
                 : "=r"(old) : "l"(ctr) : "memory");
    return old;
}

__device__ __forceinline__ unsigned int ld_acquire(const unsigned int* p) {
    unsigned int v;
    asm volatile("ld.acquire.gpu.u32 %0, [%1];" : "=r"(v) : "l"(p) : "memory");
    return v;
}

struct Stats { float svp, sup_, sup2, bce, cnts; };

__device__ __forceinline__ Stats block_stats(const float4& x4, const float4& t4,
                                             const int4& s4, const int4& i4) {
    Stats r = {0.f, 0.f, 0.f, 0.f, 0.f};
    const float xs[4] = {x4.x, x4.y, x4.z, x4.w};
    const float ts[4] = {t4.x, t4.y, t4.z, t4.w};
    const int   ss[4] = {s4.x, s4.y, s4.z, s4.w};
    const int   is_[4]= {i4.x, i4.y, i4.z, i4.w};
    #pragma unroll
    for (int j = 0; j < 4; ++j) {
        const float x  = xs[j];
        const bool  su = ss[j] != 0;
        const bool  ig = is_[j] != 0;
        const bool  vld = !ig;
        const bool  unc = vld && !su;

        const float p = __fdividef(1.0f, 1.0f + __expf(-x));
        if (vld) r.svp += p;
        if (unc) { r.sup_ += p; r.sup2 = fmaf(p, p, r.sup2); }
        /* targets are exactly 0.0 or 1.0: BCE = -log(t ? p : 1-p) */
        if (su)  r.bce -= __logf(ts[j] > 0.5f ? p : 1.0f - p);
        /* pack counts: vld + 256*unc + 65536*sup (sum < 2^24, exact) */
        r.cnts += (vld ? 1.0f : 0.0f) + (unc ? 256.0f : 0.0f) + (su ? 65536.0f : 0.0f);
    }
    return r;
}

__global__ void __launch_bounds__(TPB, 4) fused_kernel(
    const float4* __restrict__ logits,
    const float4* __restrict__ targets,
    const int4*   __restrict__ sup_mask,
    const int4*   __restrict__ ign_mask,
    const int*    __restrict__ kv_indices,
    const int*    __restrict__ kv_num_blocks,
    float*        __restrict__ out)
{
    const int lane = threadIdx.x & 31;
    const int wid  = threadIdx.x >> 5;
    const int cta  = blockIdx.x;
    const int b    = cta >> 5;                   /* batch: 32 CTAs each */
    const int base = b << 9;                     /* batch * 512 */
    const int blk0 = base + ((cta & 31) << 4) + wid * 2;  /* 2 blocks / warp */

    __shared__ float4 sh_vp4[NBB / 2];           /* whole-batch vp table: 4 KB */
    __shared__ float2 sh_bce[8];
    __shared__ float2 sh_sq[16];
    __shared__ int    sh_role;

    float2* sh_vp = reinterpret_cast<float2*>(sh_vp4);

    /* ---- prefetch phase-B operands (latency hides under phase A) ---- */
    const int idx0 = kv_indices[blk0 * KK + lane];
    const int idx1 = kv_indices[(blk0 + 1) * KK + lane];
    const int knb0 = kv_num_blocks[blk0];
    const int knb1 = kv_num_blocks[blk0 + 1];

    /* ============ Phase A: 2 blocks per warp, fully unrolled (MLP=8) ========== */
    Stats A, B;
    {
        const int v0 = blk0 * 32 + lane;
        const int v1 = v0 + 32;

        const float4 xa = logits[v0],   xb = logits[v1];
        const float4 ta = targets[v0],  tb = targets[v1];
        const int4   sa = sup_mask[v0], sb = sup_mask[v1];
        const int4   ia = ign_mask[v0], ib = ign_mask[v1];

        A = block_stats(xa, ta, sa, ia);
        B = block_stats(xb, tb, sb, ib);

        warp_sum2(A.svp,  B.svp);
        warp_sum2(A.sup_, B.sup_);
        warp_sum2(A.sup2, B.sup2);
        warp_sum2(A.bce,  B.bce);
        warp_sum2(A.cnts, B.cnts);

        if (lane == 0) {
            const int ca = (int)A.cnts, cb = (int)B.cnts;
            g_vp[blk0]     = make_float2((float)(ca & 255), A.svp);
            g_vp[blk0 + 1] = make_float2((float)(cb & 255), B.svp);
            /* unc sums stay in lane-0 registers (A,B) — no global round-trip */
            sh_bce[wid] = make_float2(A.bce + B.bce, (float)((ca >> 16) + (cb >> 16)));
        }
    }
    __syncthreads();
    if (threadIdx.x == 0) {
        float s = 0.f, c = 0.f;
        #pragma unroll
        for (int w = 0; w < 8; ++w) { s += sh_bce[w].x; c += sh_bce[w].y; }
        g_cta_bce[cta] = make_float2(s, c);
        /* per-batch barrier: the 32 CTAs of this batch */
        const unsigned int old = arrive_acq_rel(&g_barA[b]);
        if (old != CTAB - 1) {
            while (ld_acquire(&g_barA[b]) < CTAB) __nanosleep(32);
        }
    }
    __syncthreads();

    /* ---- stage the whole batch's vp table into smem (coalesced, 1 ld/thread) */
    sh_vp4[threadIdx.x] = reinterpret_cast<const float4*>(g_vp + base)[threadIdx.x];
    __syncthreads();

    /* ============ Phase B: 2 query blocks per warp, all-smem gathers ========= */
    {
        float2 vp0 = sh_vp[idx0];                  /* LDS, ~29cy */
        float2 vp1 = sh_vp[idx1];

        if (lane >= knb0) { vp0.x = 0.f; vp0.y = 0.f; }
        if (lane >= knb1) { vp1.x = 0.f; vp1.y = 0.f; }
        float cv0 = vp0.x, sp0 = vp0.y, cv1 = vp1.x, sp1 = vp1.y;
        warp_sum2(cv0, sp0);
        warp_sum2(cv1, sp1);

        if (lane == 0) {
            const float qunc0 = (float)(((int)A.cnts >> 8) & 255);
            const float qunc1 = (float)(((int)B.cnts >> 8) & 255);
            const float nm0 = __fdividef(sp0, fmaxf(cv0, 1.0f));
            const float nm1 = __fdividef(sp1, fmaxf(cv1, 1.0f));
            const bool ok0 = (qunc0 > 0.f) && (knb0 > 0) && (cv0 > 0.f);
            const bool ok1 = (qunc1 > 0.f) && (knb1 > 0) && (cv1 > 0.f);
            const float sq0 = A.sup2 - 2.0f * nm0 * A.sup_ + nm0 * nm0 * qunc0;
            const float sq1 = B.sup2 - 2.0f * nm1 * B.sup_ + nm1 * nm1 * qunc1;
            sh_sq[wid * 2]     = make_float2(ok0 ? sq0 : 0.f, ok0 ? qunc0 : 0.f);
            sh_sq[wid * 2 + 1] = make_float2(ok1 ? sq1 : 0.f, ok1 ? qunc1 : 0.f);
        }
    }
    __syncthreads();
    if (threadIdx.x == 0) {
        float s = 0.f, q = 0.f;
        #pragma unroll
        for (int i = 0; i < 16; ++i) { s += sh_sq[i].x; q += sh_sq[i].y; }
        g_cta_sq[cta] = make_float2(s, q);
        /* per-batch completion: last of the 32 CTAs becomes batch reducer */
        const unsigned int old = arrive_acq_rel(&g_barB[b]);
        sh_role = (old == CTAB - 1);
    }
    __syncthreads();
    if (!sh_role || wid != 0) return;

    /* ============ Batch tail (one warp): reduce this batch's 32 CTAs ========= */
    {
        const float2 pc = g_cta_bce[(b << 5) + lane];   /* coalesced 256B */
        const float2 ps = g_cta_sq [(b << 5) + lane];
        float bs = pc.x, bc = pc.y;
        float sq = ps.x, qu = ps.y;
        warp_sum2(bs, bc);
        warp_sum2(sq, qu);

        int fin = 0;
        if (lane == 0) {
            g_batch[b] = make_float4(sq, qu, bs, bc);
            const unsigned int old = arrive_acq_rel(&g_gdone);
            fin = (old == BB - 1);
        }
        fin = __shfl_sync(0xFFFFFFFFu, fin, 0);
        if (!fin) return;

        /* ======== Final combine (one warp of the last batch reducer) ======== */
        (void)ld_acquire(&g_gdone);                     /* per-lane acquire */
        float4 gb = make_float4(0.f, 0.f, 0.f, 0.f);
        if (lane < BB) gb = g_batch[lane];

        float tbs = gb.z, tbc = gb.w;
        warp_sum2(tbs, tbc);                            /* BCE totals */
        float term = (gb.y > 0.f) ? __fdividef(gb.x, fmaxf(gb.y, 1.0f)) : 0.0f;
        float nv   = (gb.y > 0.f) ? 1.0f : 0.0f;
        warp_sum2(term, nv);

        if (lane == 0) {
            const float bce = __fdividef(tbs, fmaxf(tbc, 1.0f));
            out[0] = bce + GW * __fdividef(term, fmaxf(nv, 1.0f));
            /* self-reset for graph replay (all CTAs already passed counters) */
            #pragma unroll
            for (int i = 0; i < BB; ++i) { g_barA[i] = 0; g_barB[i] = 0; }
            g_gdone = 0;
        }
    }
}

extern "C" void kernel_launch(void* const* d_in, const int* in_sizes, int n_in,
                              void* d_out, int out_size)
{
    const float4* logits        = (const float4*)d_in[0];
    const float4* targets       = (const float4*)d_in[1];
    const int4*   sup_mask      = (const int4*)d_in[2];
    const int4*   ign_mask      = (const int4*)d_in[3];
    const int*    kv_indices    = (const int*)d_in[4];
    const int*    kv_num_blocks = (const int*)d_in[5];
    float* out = (float*)d_out;

    fused_kernel<<<GRID, TPB>>>(logits, targets, sup_mask, ign_mask,
                                kv_indices, kv_num_blocks, out);
}

// round 14
// speedup vs baseline: 1.1775x; 1.0175x over previous
#include <cuda_runtime.h>
#include <math.h>

#define BB    16
#define NBB   512
#define KK    32
#define NBLK  (BB * NBB)      /* 8192 (b, nb) blocks */
#define GW    0.3f
#define GRID  512             /* 32 CTAs per batch; 4 CTAs/SM resident */
#define TPB   256
#define CTAB  32              /* CTAs per batch */

/* ---- scratch (device globals; no allocation) ---- */
__device__ float2 g_vp   [NBLK];    /* (cnt_vld, sum_vld_p) */
__device__ float4 g_cta  [GRID];    /* per-CTA (bce_sum, bce_cnt, sq, qu) */
__device__ float4 g_batch[BB];      /* per-batch (sq, qu, bce_sum, bce_cnt) */
__device__ unsigned int g_barA[BB];
__device__ unsigned int g_barB[BB];
__device__ unsigned int g_gdone = 0;

/* reduce two floats simultaneously: 2 shfl + 1 packed f32x2 add per level */
__device__ __forceinline__ void warp_sum2(float& a, float& b) {
    unsigned long long p;
    asm("mov.b64 %0, {%1, %2};" : "=l"(p) : "f"(a), "f"(b));
    #pragma unroll
    for (int o = 16; o > 0; o >>= 1) {
        unsigned int lo = (unsigned int)p, hi = (unsigned int)(p >> 32);
        lo = __shfl_down_sync(0xFFFFFFFFu, lo, o);
        hi = __shfl_down_sync(0xFFFFFFFFu, hi, o);
        unsigned long long q = ((unsigned long long)hi << 32) | lo;
        asm("add.rn.f32x2 %0, %1, %2;" : "=l"(p) : "l"(p), "l"(q));
    }
    asm("mov.b64 {%0, %1}, %2;" : "=f"(a), "=f"(b) : "l"(p));
}

__device__ __forceinline__ unsigned int arrive_acq_rel(unsigned int* ctr) {
    unsigned int old;
    asm volatile("atom.acq_rel.gpu.add.u32 %0, [%1], 1;"
                 : "=r"(old) : "l"(ctr) : "memory");
    return old;
}

__device__ __forceinline__ unsigned int ld_acquire(const unsigned int* p) {
    unsigned int v;
    asm volatile("ld.acquire.gpu.u32 %0, [%1];" : "=r"(v) : "l"(p) : "memory");
    return v;
}

struct Stats { float svp, sup_, sup2, bce, cnts; };

__device__ __forceinline__ Stats block_stats(const float4& x4, const float4& t4,
                                             const int4& s4, const int4& i4) {
    Stats r = {0.f, 0.f, 0.f, 0.f, 0.f};
    const float xs[4] = {x4.x, x4.y, x4.z, x4.w};
    const float ts[4] = {t4.x, t4.y, t4.z, t4.w};
    const int   ss[4] = {s4.x, s4.y, s4.z, s4.w};
    const int   is_[4]= {i4.x, i4.y, i4.z, i4.w};
    #pragma unroll
    for (int j = 0; j < 4; ++j) {
        const float x  = xs[j];
        const bool  su = ss[j] != 0;
        const bool  ig = is_[j] != 0;
        const bool  vld = !ig;
        const bool  unc = vld && !su;

        const float p = __fdividef(1.0f, 1.0f + __expf(-x));
        if (vld) r.svp += p;
        if (unc) { r.sup_ += p; r.sup2 = fmaf(p, p, r.sup2); }
        /* targets are exactly 0.0 or 1.0: BCE = -log(t ? p : 1-p) */
        if (su)  r.bce -= __logf(ts[j] > 0.5f ? p : 1.0f - p);
        /* pack counts: vld + 256*unc + 65536*sup (sum < 2^24, exact) */
        r.cnts += (vld ? 1.0f : 0.0f) + (unc ? 256.0f : 0.0f) + (su ? 65536.0f : 0.0f);
    }
    return r;
}

__global__ void __launch_bounds__(TPB, 4) fused_kernel(
    const float4* __restrict__ logits,
    const float4* __restrict__ targets,
    const int4*   __restrict__ sup_mask,
    const int4*   __restrict__ ign_mask,
    const int*    __restrict__ kv_indices,
    const int*    __restrict__ kv_num_blocks,
    float*        __restrict__ out)
{
    const int lane = threadIdx.x & 31;
    const int wid  = threadIdx.x >> 5;
    const int cta  = blockIdx.x;
    const int b    = cta >> 5;                   /* batch: 32 CTAs each */
    const int base = b << 9;                     /* batch * 512 */
    const int blk0 = base + ((cta & 31) << 4) + wid * 2;  /* 2 blocks / warp */

    __shared__ float4 sh_vp4[NBB / 2];           /* whole-batch vp table: 4 KB */
    __shared__ float2 sh_bce[8];
    __shared__ float2 sh_sq[16];
    __shared__ int    sh_role;

    float2* sh_vp = reinterpret_cast<float2*>(sh_vp4);

    /* ---- prefetch phase-B operands (latency hides under phase A) ---- */
    const int idx0 = kv_indices[blk0 * KK + lane];
    const int idx1 = kv_indices[(blk0 + 1) * KK + lane];
    const int knb0 = kv_num_blocks[blk0];
    const int knb1 = kv_num_blocks[blk0 + 1];

    /* ============ Phase A: 2 blocks per warp, fully unrolled (MLP=8) ========== */
    Stats A, B;
    {
        const int v0 = blk0 * 32 + lane;
        const int v1 = v0 + 32;

        const float4 xa = logits[v0],   xb = logits[v1];
        const float4 ta = targets[v0],  tb = targets[v1];
        const int4   sa = sup_mask[v0], sb = sup_mask[v1];
        const int4   ia = ign_mask[v0], ib = ign_mask[v1];

        A = block_stats(xa, ta, sa, ia);
        B = block_stats(xb, tb, sb, ib);

        warp_sum2(A.svp,  B.svp);
        warp_sum2(A.sup_, B.sup_);
        warp_sum2(A.sup2, B.sup2);
        warp_sum2(A.bce,  B.bce);
        warp_sum2(A.cnts, B.cnts);

        if (lane == 0) {
            const int ca = (int)A.cnts, cb = (int)B.cnts;
            g_vp[blk0]     = make_float2((float)(ca & 255), A.svp);
            g_vp[blk0 + 1] = make_float2((float)(cb & 255), B.svp);
            sh_bce[wid] = make_float2(A.bce + B.bce, (float)((ca >> 16) + (cb >> 16)));
        }
    }
    __syncthreads();

    /* warp 0: CTA bce reduce (registers), then barrier arrive + poll by lane 0 */
    float cta_bs = 0.f, cta_bc = 0.f;
    if (wid == 0) {
        const float2 t = (lane < 8) ? sh_bce[lane] : make_float2(0.f, 0.f);
        cta_bs = t.x; cta_bc = t.y;
        warp_sum2(cta_bs, cta_bc);          /* lane 0 holds CTA totals in regs */
        if (lane == 0) {
            const unsigned int old = arrive_acq_rel(&g_barA[b]);
            if (old != CTAB - 1) {
                while (ld_acquire(&g_barA[b]) < CTAB) __nanosleep(32);
            }
        }
    }
    __syncthreads();

    /* ---- stage the whole batch's vp table into smem (coalesced, 1 ld/thread) */
    sh_vp4[threadIdx.x] = reinterpret_cast<const float4*>(g_vp + base)[threadIdx.x];
    __syncthreads();

    /* ============ Phase B: 2 query blocks per warp, all-smem gathers ========= */
    {
        float2 vp0 = sh_vp[idx0];
        float2 vp1 = sh_vp[idx1];

        if (lane >= knb0) { vp0.x = 0.f; vp0.y = 0.f; }
        if (lane >= knb1) { vp1.x = 0.f; vp1.y = 0.f; }
        float cv0 = vp0.x, sp0 = vp0.y, cv1 = vp1.x, sp1 = vp1.y;
        warp_sum2(cv0, sp0);
        warp_sum2(cv1, sp1);

        if (lane == 0) {
            const float qunc0 = (float)(((int)A.cnts >> 8) & 255);
            const float qunc1 = (float)(((int)B.cnts >> 8) & 255);
            const float nm0 = __fdividef(sp0, fmaxf(cv0, 1.0f));
            const float nm1 = __fdividef(sp1, fmaxf(cv1, 1.0f));
            const bool ok0 = (qunc0 > 0.f) && (knb0 > 0) && (cv0 > 0.f);
            const bool ok1 = (qunc1 > 0.f) && (knb1 > 0) && (cv1 > 0.f);
            const float sq0 = A.sup2 - 2.0f * nm0 * A.sup_ + nm0 * nm0 * qunc0;
            const float sq1 = B.sup2 - 2.0f * nm1 * B.sup_ + nm1 * nm1 * qunc1;
            sh_sq[wid * 2]     = make_float2(ok0 ? sq0 : 0.f, ok0 ? qunc0 : 0.f);
            sh_sq[wid * 2 + 1] = make_float2(ok1 ? sq1 : 0.f, ok1 ? qunc1 : 0.f);
        }
    }
    __syncthreads();

    /* warp 0: CTA sq reduce + single float4 partial + barB arrive */
    if (wid == 0) {
        const float2 t = (lane < 16) ? sh_sq[lane] : make_float2(0.f, 0.f);
        float sq = t.x, qu = t.y;
        warp_sum2(sq, qu);
        if (lane == 0) {
            g_cta[cta] = make_float4(cta_bs, cta_bc, sq, qu);  /* one STG.128 */
            const unsigned int old = arrive_acq_rel(&g_barB[b]);
            sh_role = (old == CTAB - 1);
        }
    }
    __syncthreads();
    if (!sh_role || wid != 0) return;

    /* ============ Batch tail (one warp): reduce this batch's 32 CTAs ========= */
    {
        const float4 pc = g_cta[(b << 5) + lane];   /* one coalesced 512B load */
        float bs = pc.x, bc = pc.y;
        float sq = pc.z, qu = pc.w;
        warp_sum2(bs, bc);
        warp_sum2(sq, qu);

        int fin = 0;
        if (lane == 0) {
            g_batch[b] = make_float4(sq, qu, bs, bc);
            const unsigned int old = arrive_acq_rel(&g_gdone);
            fin = (old == BB - 1);
        }
        fin = __shfl_sync(0xFFFFFFFFu, fin, 0);
        if (!fin) return;

        /* ======== Final combine (one warp of the last batch reducer) ======== */
        (void)ld_acquire(&g_gdone);
        float4 gb = make_float4(0.f, 0.f, 0.f, 0.f);
        if (lane < BB) gb = g_batch[lane];

        float tbs = gb.z, tbc = gb.w;
        warp_sum2(tbs, tbc);
        float term = (gb.y > 0.f) ? __fdividef(gb.x, fmaxf(gb.y, 1.0f)) : 0.0f;
        float nv   = (gb.y > 0.f) ? 1.0f : 0.0f;
        warp_sum2(term, nv);

        if (lane == 0) {
            const float bce = __fdividef(tbs, fmaxf(tbc, 1.0f));
            out[0] = bce + GW * __fdividef(term, fmaxf(nv, 1.0f));
            /* self-reset for graph replay (all CTAs already passed counters) */
            #pragma unroll
            for (int i = 0; i < BB; ++i) { g_barA[i] = 0; g_barB[i] = 0; }
            g_gdone = 0;
        }
    }
}

extern "C" void kernel_launch(void* const* d_in, const int* in_sizes, int n_in,
                              void* d_out, int out_size)
{
    const float4* logits        = (const float4*)d_in[0];
    const float4* targets       = (const float4*)d_in[1];
    const int4*   sup_mask      = (const int4*)d_in[2];
    const int4*   ign_mask      = (const int4*)d_in[3];
    const int*    kv_indices    = (const int*)d_in[4];
    const int*    kv_num_blocks = (const int*)d_in[5];
    float* out = (float*)d_out;

    fused_kernel<<<GRID, TPB>>>(logits, targets, sup_mask, ign_mask,
                                kv_indices, kv_num_blocks, out);
}